// round 1
// baseline (speedup 1.0000x reference)
#include <cuda_runtime.h>
#include <math.h>

#define BNUM 32
#define NTOK 4096
#define FDIN 768
#define DD 256
#define NS 8
#define MROWS (BNUM * NTOK)   // 131072
#define ITERS 3

// ---------------- scratch (static __device__ — no allocation) ----------------
__device__ float g_mean[MROWS];
__device__ float g_rstd[MROWS];
__device__ float g_h1[(size_t)MROWS * FDIN];     // 402 MB
__device__ float g_h2[(size_t)MROWS * DD];       // 134 MB
__device__ float g_feats[(size_t)MROWS * DD];    // 134 MB
__device__ float g_keys[(size_t)MROWS * DD];     // 134 MB
__device__ float g_vals[(size_t)MROWS * DD];     // 134 MB
__device__ float g_wkT[DD * DD];
__device__ float g_wvT[DD * DD];
__device__ float g_wqT[DD * DD];
__device__ float g_wihT[DD * 3 * DD];            // [256][768]
__device__ float g_whhT[DD * 3 * DD];
__device__ float g_slots[BNUM * NS * DD];
__device__ float g_q[BNUM * NS * DD];
__device__ float g_U[BNUM * NS * DD];
__device__ float g_rowsum[BNUM * NS];

// ---------------- utility kernels ----------------
__global__ void transpose_kernel(const float* __restrict__ in,
                                 float* __restrict__ out, int R, int C) {
    int idx = blockIdx.x * 256 + threadIdx.x;
    if (idx < R * C) {
        int r = idx / C, c = idx % C;
        out[c * R + r] = in[idx];
    }
}

__global__ void slots_init_kernel(const float* __restrict__ si) {
    int i = blockIdx.x * 256 + threadIdx.x;   // 65536 total
    g_slots[i] = si[i & (NS * DD - 1)];
}

__global__ void zero_ur_kernel() {
    int i = blockIdx.x * 256 + threadIdx.x;
    g_U[i] = 0.f;
    if (i < BNUM * NS) g_rowsum[i] = 0.f;
}

__global__ void copy_out_kernel(float* __restrict__ out) {
    int i = blockIdx.x * 256 + threadIdx.x;
    out[i] = g_slots[i];
}

// ---------------- LN stats for inputs (warp per row of 768) ----------------
__global__ void ln_stats_kernel(const float* __restrict__ x) {
    int row = blockIdx.x * 8 + (threadIdx.x >> 5);
    int lane = threadIdx.x & 31;
    const float* p = x + (size_t)row * FDIN;
    float s = 0.f, ss = 0.f;
    #pragma unroll
    for (int j = lane; j < FDIN; j += 32) { float v = p[j]; s += v; ss += v * v; }
    #pragma unroll
    for (int o = 16; o; o >>= 1) {
        s  += __shfl_xor_sync(0xffffffffu, s, o);
        ss += __shfl_xor_sync(0xffffffffu, ss, o);
    }
    float m = s * (1.f / FDIN);
    float var = ss * (1.f / FDIN) - m * m;
    if (lane == 0) { g_mean[row] = m; g_rstd[row] = rsqrtf(var + 1e-5f); }
}

// ---------------- SGEMM: C[M,N] = op(A[M,K]) @ B[K,N] (+bias)(relu) ----------
template<bool FLN, bool RELU, bool BIAS>
__global__ void __launch_bounds__(256)
sgemm_kernel(const float* __restrict__ A, const float* __restrict__ Bw,
             const float* __restrict__ bias, float* __restrict__ C,
             int M, int Nn, int K,
             const float* __restrict__ lng, const float* __restrict__ lnb) {
    const int BK = 8;
    __shared__ float As[BK][128];
    __shared__ float Bs[BK][128];
    int bx = blockIdx.x;   // N tiles
    int by = blockIdx.y;   // M tiles
    int tid = threadIdx.x;
    int tr = tid >> 4;            // 0..15
    int tc = tid & 15;            // 0..15
    int aRow = tid >> 1;          // 0..127
    int aCol = (tid & 1) * 4;     // 0 or 4
    int bRow = tid >> 5;          // 0..7
    int bCol = (tid & 31) * 4;

    const float* Aptr = A + (size_t)(by * 128 + aRow) * K + aCol;
    const float* Bptr = Bw + (size_t)bRow * Nn + bx * 128 + bCol;
    float lm = 0.f, lr = 0.f;
    if (FLN) { lm = g_mean[by * 128 + aRow]; lr = g_rstd[by * 128 + aRow]; }

    float acc[8][8];
    #pragma unroll
    for (int i = 0; i < 8; i++)
        #pragma unroll
        for (int j = 0; j < 8; j++) acc[i][j] = 0.f;

    for (int k0 = 0; k0 < K; k0 += BK) {
        float4 av = *(const float4*)(Aptr);
        if (FLN) {
            int kk = k0 + aCol;
            av.x = (av.x - lm) * lr * lng[kk + 0] + lnb[kk + 0];
            av.y = (av.y - lm) * lr * lng[kk + 1] + lnb[kk + 1];
            av.z = (av.z - lm) * lr * lng[kk + 2] + lnb[kk + 2];
            av.w = (av.w - lm) * lr * lng[kk + 3] + lnb[kk + 3];
        }
        As[aCol + 0][aRow] = av.x;
        As[aCol + 1][aRow] = av.y;
        As[aCol + 2][aRow] = av.z;
        As[aCol + 3][aRow] = av.w;
        *(float4*)&Bs[bRow][bCol] = *(const float4*)(Bptr);
        __syncthreads();
        Aptr += BK;
        Bptr += (size_t)BK * Nn;
        #pragma unroll
        for (int kk = 0; kk < BK; kk++) {
            float ra[8], rb[8];
            #pragma unroll
            for (int i = 0; i < 8; i++) ra[i] = As[kk][tr * 8 + i];
            #pragma unroll
            for (int j = 0; j < 8; j++) rb[j] = Bs[kk][tc * 8 + j];
            #pragma unroll
            for (int i = 0; i < 8; i++)
                #pragma unroll
                for (int j = 0; j < 8; j++) acc[i][j] += ra[i] * rb[j];
        }
        __syncthreads();
    }

    #pragma unroll
    for (int i = 0; i < 8; i++) {
        int row = by * 128 + tr * 8 + i;
        float* cp = C + (size_t)row * Nn + bx * 128 + tc * 8;
        #pragma unroll
        for (int j = 0; j < 8; j++) {
            float v = acc[i][j];
            if (BIAS) v += bias[bx * 128 + tc * 8 + j];
            if (RELU) v = fmaxf(v, 0.f);
            cp[j] = v;
        }
    }
}

// ---------------- block mean/var helper for 256-wide rows --------------------
__device__ __forceinline__ float2 block_meanvar_256(float v, float* r1, float* r2) {
    float s = v, q = v * v;
    #pragma unroll
    for (int o = 16; o; o >>= 1) {
        s += __shfl_xor_sync(0xffffffffu, s, o);
        q += __shfl_xor_sync(0xffffffffu, q, o);
    }
    int w = threadIdx.x >> 5, lane = threadIdx.x & 31;
    if (lane == 0) { r1[w] = s; r2[w] = q; }
    __syncthreads();
    float sum = 0.f, sq = 0.f;
    #pragma unroll
    for (int i = 0; i < 8; i++) { sum += r1[i]; sq += r2[i]; }
    __syncthreads();
    float m = sum * (1.f / 256.f);
    float var = sq * (1.f / 256.f) - m * m;
    return make_float2(m, rsqrtf(var + 1e-5f));
}

// ---------------- LN over 256-wide rows: feats = LN(h2) ----------------------
__global__ void ln256_kernel(const float* __restrict__ x, float* __restrict__ y,
                             const float* __restrict__ g, const float* __restrict__ b) {
    __shared__ float r1[8], r2[8];
    size_t row = blockIdx.x;
    int tid = threadIdx.x;
    float v = x[row * DD + tid];
    float2 mv = block_meanvar_256(v, r1, r2);
    y[row * DD + tid] = (v - mv.x) * mv.y * g[tid] + b[tid];
}

// ---------------- q = LN(slots) @ wq^T (block per (b,s) row) -----------------
__global__ void qproj_kernel(const float* __restrict__ ng, const float* __restrict__ nb) {
    __shared__ float sln[DD];
    __shared__ float r1[8], r2[8];
    int row = blockIdx.x, tid = threadIdx.x;
    float v = g_slots[row * DD + tid];
    float2 mv = block_meanvar_256(v, r1, r2);
    sln[tid] = (v - mv.x) * mv.y * ng[tid] + nb[tid];
    __syncthreads();
    float acc = 0.f;
    #pragma unroll 8
    for (int d = 0; d < DD; d++) acc += sln[d] * g_wqT[d * DD + tid];
    g_q[row * DD + tid] = acc;
}

// ---------------- attention: U += attn_u @ V, rowsum += sum_t attn_u ---------
__global__ void __launch_bounds__(256)
attn_kernel() {
    int b = blockIdx.x, ch = blockIdx.y;
    int warp = threadIdx.x >> 5, lane = threadIdx.x & 31;
    __shared__ float qs[NS * DD];
    __shared__ float dots[8][NS];
    for (int i = threadIdx.x; i < NS * DD; i += 256) qs[i] = g_q[b * NS * DD + i];
    __syncthreads();
    float qreg[8];
    #pragma unroll
    for (int j = 0; j < 8; j++) qreg[j] = qs[warp * DD + lane + 32 * j];
    float uacc[8];
    #pragma unroll
    for (int j = 0; j < 8; j++) uacc[j] = 0.f;
    float rsum = 0.f;
    const float scale = 0.0625f;   // 256^-0.5
    int t0 = ch * 512;
    const float* kb = g_keys + ((size_t)b * NTOK + t0) * DD;
    const float* vb = g_vals + ((size_t)b * NTOK + t0) * DD;

    for (int tt = 0; tt < 512; tt += 8) {
        // phase 1: this warp's slot, 8 tokens of dots
        #pragma unroll
        for (int u = 0; u < 8; u++) {
            const float* kp = kb + (size_t)(tt + u) * DD;
            float d = 0.f;
            #pragma unroll
            for (int j = 0; j < 8; j++) d += qreg[j] * kp[lane + 32 * j];
            #pragma unroll
            for (int o = 16; o; o >>= 1) d += __shfl_xor_sync(0xffffffffu, d, o);
            if (lane == 0) dots[u][warp] = d * scale;
        }
        __syncthreads();
        // phase 2: softmax over slots per token, accumulate updates
        #pragma unroll
        for (int u = 0; u < 8; u++) {
            float mx = -1e30f;
            #pragma unroll
            for (int s2 = 0; s2 < NS; s2++) mx = fmaxf(mx, dots[u][s2]);
            float sume = 0.f;
            #pragma unroll
            for (int s2 = 0; s2 < NS; s2++) sume += expf(dots[u][s2] - mx);
            float a = expf(dots[u][warp] - mx) / sume + 1e-8f;
            const float* vp = vb + (size_t)(tt + u) * DD;
            #pragma unroll
            for (int j = 0; j < 8; j++) uacc[j] += a * vp[lane + 32 * j];
            rsum += a;
        }
        __syncthreads();
    }
    float* up = g_U + (b * NS + warp) * DD;
    #pragma unroll
    for (int j = 0; j < 8; j++) atomicAdd(&up[lane + 32 * j], uacc[j]);
    if (lane == 0) atomicAdd(&g_rowsum[b * NS + warp], rsum);
}

// ---------------- GRU cell + residual pre-LN MLP (block per (b,s) row) -------
__global__ void __launch_bounds__(256)
gru_mlp_kernel(const float* __restrict__ bih, const float* __restrict__ bhh,
               const float* __restrict__ mlng, const float* __restrict__ mlnb,
               const float* __restrict__ w1, const float* __restrict__ b1,
               const float* __restrict__ w2, const float* __restrict__ b2) {
    __shared__ float upd[DD], sp[DD], mm[DD];
    __shared__ float hh[4 * DD];
    __shared__ float r1[8], r2[8];
    int row = blockIdx.x, tid = threadIdx.x;
    float rs = g_rowsum[row];
    upd[tid] = g_U[row * DD + tid] / rs;
    sp[tid]  = g_slots[row * DD + tid];
    __syncthreads();

    float ir = bih[tid], iz = bih[tid + 256], inn = bih[tid + 512];
    float hr = bhh[tid], hz = bhh[tid + 256], hn = bhh[tid + 512];
    #pragma unroll 4
    for (int d = 0; d < DD; d++) {
        float u = upd[d], s = sp[d];
        const float* wi = &g_wihT[d * 768];
        const float* wh = &g_whhT[d * 768];
        ir  += u * wi[tid];       hr  += s * wh[tid];
        iz  += u * wi[tid + 256]; hz  += s * wh[tid + 256];
        inn += u * wi[tid + 512]; hn  += s * wh[tid + 512];
    }
    float r = 1.f / (1.f + expf(-(ir + hr)));
    float z = 1.f / (1.f + expf(-(iz + hz)));
    float n = tanhf(inn + r * hn);
    float h = (1.f - z) * n + z * sp[tid];
    __syncthreads();   // done reading sp/upd before any reuse

    // pre-LN
    float2 mv = block_meanvar_256(h, r1, r2);
    mm[tid] = (h - mv.x) * mv.y * mlng[tid] + mlnb[tid];
    __syncthreads();

    // MLP layer 1: 1024 outs, 4 per thread (coalesced over w1 columns)
    #pragma unroll
    for (int jj = 0; jj < 4; jj++) {
        int o = tid + jj * 256;
        float a = b1[o];
        #pragma unroll 8
        for (int d = 0; d < DD; d++) a += mm[d] * w1[d * 1024 + o];
        hh[o] = fmaxf(a, 0.f);
    }
    __syncthreads();
    // MLP layer 2
    float a2 = b2[tid];
    #pragma unroll 8
    for (int j = 0; j < 1024; j++) a2 += hh[j] * w2[j * 256 + tid];
    g_slots[row * DD + tid] = h + a2;
}

// ---------------- launch ----------------
extern "C" void kernel_launch(void* const* d_in, const int* in_sizes, int n_in,
                              void* d_out, int out_size) {
    const float* inputs   = (const float*)d_in[0];
    const float* slots_in = (const float*)d_in[1];
    const float* ln1g = (const float*)d_in[2];
    const float* ln1b = (const float*)d_in[3];
    const float* w1   = (const float*)d_in[4];
    const float* b1   = (const float*)d_in[5];
    const float* w2   = (const float*)d_in[6];
    const float* b2   = (const float*)d_in[7];
    const float* ln2g = (const float*)d_in[8];
    const float* ln2b = (const float*)d_in[9];
    const float* wq   = (const float*)d_in[10];
    const float* wk   = (const float*)d_in[11];
    const float* wv   = (const float*)d_in[12];
    const float* normg = (const float*)d_in[13];
    const float* normb = (const float*)d_in[14];
    const float* gwih = (const float*)d_in[15];
    const float* gwhh = (const float*)d_in[16];
    const float* gbih = (const float*)d_in[17];
    const float* gbhh = (const float*)d_in[18];
    const float* mlng = (const float*)d_in[19];
    const float* mlnb = (const float*)d_in[20];
    const float* mw1  = (const float*)d_in[21];
    const float* mb1  = (const float*)d_in[22];
    const float* mw2  = (const float*)d_in[23];
    const float* mb2  = (const float*)d_in[24];
    float* out = (float*)d_out;

    float *p_wkT, *p_wvT, *p_wqT, *p_wihT, *p_whhT;
    float *p_h1, *p_h2, *p_feats, *p_keys, *p_vals;
    cudaGetSymbolAddress((void**)&p_wkT,  g_wkT);
    cudaGetSymbolAddress((void**)&p_wvT,  g_wvT);
    cudaGetSymbolAddress((void**)&p_wqT,  g_wqT);
    cudaGetSymbolAddress((void**)&p_wihT, g_wihT);
    cudaGetSymbolAddress((void**)&p_whhT, g_whhT);
    cudaGetSymbolAddress((void**)&p_h1,   g_h1);
    cudaGetSymbolAddress((void**)&p_h2,   g_h2);
    cudaGetSymbolAddress((void**)&p_feats, g_feats);
    cudaGetSymbolAddress((void**)&p_keys, g_keys);
    cudaGetSymbolAddress((void**)&p_vals, g_vals);

    // weight transposes (tiny)
    transpose_kernel<<<(DD * DD + 255) / 256, 256>>>(wk, p_wkT, DD, DD);
    transpose_kernel<<<(DD * DD + 255) / 256, 256>>>(wv, p_wvT, DD, DD);
    transpose_kernel<<<(DD * DD + 255) / 256, 256>>>(wq, p_wqT, DD, DD);
    transpose_kernel<<<(3 * DD * DD + 255) / 256, 256>>>(gwih, p_wihT, 3 * DD, DD);
    transpose_kernel<<<(3 * DD * DD + 255) / 256, 256>>>(gwhh, p_whhT, 3 * DD, DD);

    // feature path
    ln_stats_kernel<<<MROWS / 8, 256>>>(inputs);
    sgemm_kernel<true, true, true><<<dim3(FDIN / 128, MROWS / 128), 256>>>(
        inputs, w1, b1, p_h1, MROWS, FDIN, FDIN, ln1g, ln1b);
    sgemm_kernel<false, false, true><<<dim3(DD / 128, MROWS / 128), 256>>>(
        p_h1, w2, b2, p_h2, MROWS, DD, FDIN, nullptr, nullptr);
    ln256_kernel<<<MROWS, 256>>>(p_h2, p_feats, ln2g, ln2b);
    sgemm_kernel<false, false, false><<<dim3(DD / 128, MROWS / 128), 256>>>(
        p_feats, p_wkT, nullptr, p_keys, MROWS, DD, DD, nullptr, nullptr);
    sgemm_kernel<false, false, false><<<dim3(DD / 128, MROWS / 128), 256>>>(
        p_feats, p_wvT, nullptr, p_vals, MROWS, DD, DD, nullptr, nullptr);

    // slot init
    slots_init_kernel<<<BNUM * NS * DD / 256, 256>>>(slots_in);

    // iterations (straight-through in iter 3 is a forward identity)
    for (int t = 0; t < ITERS; t++) {
        qproj_kernel<<<BNUM * NS, 256>>>(normg, normb);
        zero_ur_kernel<<<BNUM * NS * DD / 256, 256>>>();
        attn_kernel<<<dim3(BNUM, 8), 256>>>();
        gru_mlp_kernel<<<BNUM * NS, 256>>>(gbih, gbhh, mlng, mlnb, mw1, mb1, mw2, mb2);
    }

    copy_out_kernel<<<BNUM * NS * DD / 256, 256>>>(out);
}

// round 2
// speedup vs baseline: 1.7911x; 1.7911x over previous
#include <cuda_runtime.h>
#include <math.h>

#define BNUM 32
#define NTOK 4096
#define FDIN 768
#define DD 256
#define NS 8
#define MROWS (BNUM * NTOK)   // 131072
#define ITERS 3

// ---------------- scratch (static __device__ — no allocation) ----------------
__device__ float g_mean[MROWS];
__device__ float g_rstd[MROWS];
__device__ float g_h1[(size_t)MROWS * FDIN];     // 402 MB
__device__ float g_h2[(size_t)MROWS * DD];       // 134 MB
__device__ float g_feats[(size_t)MROWS * DD];    // 134 MB
__device__ float g_keys[(size_t)MROWS * DD];     // 134 MB
__device__ float g_vals[(size_t)MROWS * DD];     // 134 MB
__device__ float g_wkT[DD * DD];
__device__ float g_wvT[DD * DD];
__device__ float g_wqT[DD * DD];
__device__ float g_wihT[DD * 3 * DD];            // [256][768]
__device__ float g_whhT[DD * 3 * DD];
__device__ float g_slots[BNUM * NS * DD];
__device__ float g_q[BNUM * NS * DD];
__device__ float g_U[BNUM * NS * DD];
__device__ float g_rowsum[BNUM * NS];

// ---------------- utility kernels ----------------
__global__ void transpose_kernel(const float* __restrict__ in,
                                 float* __restrict__ out, int R, int C) {
    int idx = blockIdx.x * 256 + threadIdx.x;
    if (idx < R * C) {
        int r = idx / C, c = idx % C;
        out[c * R + r] = in[idx];
    }
}

__global__ void slots_init_kernel(const float* __restrict__ si) {
    int i = blockIdx.x * 256 + threadIdx.x;
    g_slots[i] = si[i & (NS * DD - 1)];
}

__global__ void zero_ur_kernel() {
    int i = blockIdx.x * 256 + threadIdx.x;
    g_U[i] = 0.f;
    if (i < BNUM * NS) g_rowsum[i] = 0.f;
}

__global__ void copy_out_kernel(float* __restrict__ out) {
    int i = blockIdx.x * 256 + threadIdx.x;
    out[i] = g_slots[i];
}

// ---------------- LN stats for inputs (warp per row of 768) ----------------
__global__ void ln_stats_kernel(const float* __restrict__ x) {
    int row = blockIdx.x * 8 + (threadIdx.x >> 5);
    int lane = threadIdx.x & 31;
    const float* p = x + (size_t)row * FDIN;
    float s = 0.f, ss = 0.f;
    #pragma unroll
    for (int j = lane; j < FDIN; j += 32) { float v = p[j]; s += v; ss += v * v; }
    #pragma unroll
    for (int o = 16; o; o >>= 1) {
        s  += __shfl_xor_sync(0xffffffffu, s, o);
        ss += __shfl_xor_sync(0xffffffffu, ss, o);
    }
    float m = s * (1.f / FDIN);
    float var = ss * (1.f / FDIN) - m * m;
    if (lane == 0) { g_mean[row] = m; g_rstd[row] = rsqrtf(var + 1e-5f); }
}

// ---------------- tf32 helpers ----------------
__device__ __forceinline__ unsigned f2tf32(float f) {
    unsigned u;
    asm("cvt.rna.tf32.f32 %0, %1;" : "=r"(u) : "f"(f));
    return u;
}

__device__ __forceinline__ void mma_tf32(float* c, const unsigned* a, const unsigned* b) {
    asm volatile(
        "mma.sync.aligned.m16n8k8.row.col.f32.tf32.tf32.f32 "
        "{%0,%1,%2,%3}, {%4,%5,%6,%7}, {%8,%9}, {%0,%1,%2,%3};"
        : "+f"(c[0]), "+f"(c[1]), "+f"(c[2]), "+f"(c[3])
        : "r"(a[0]), "r"(a[1]), "r"(a[2]), "r"(a[3]), "r"(b[0]), "r"(b[1]));
}

// ---------------- TF32 tensor-core GEMM ----------------
// C[M,N] = op(A[M,K]) @ B[K,N] (+bias)(relu).  op = optional fused LayerNorm on A rows.
// Block tile 128x128, BK=16, 256 threads (8 warps in 4x2 grid, 32x64 warp tile).
template<bool FLN, bool RELU, bool BIAS>
__global__ void __launch_bounds__(256)
tf32_gemm_kernel(const float* __restrict__ A, const float* __restrict__ Bw,
                 const float* __restrict__ bias, float* __restrict__ C,
                 int M, int Nn, int K,
                 const float* __restrict__ lng, const float* __restrict__ lnb) {
    const int BK = 16;
    const int LDAS = 136;   // 128 + 8 pad: conflict-free frags + 16B aligned rows
    __shared__ unsigned As[2][BK][LDAS];
    __shared__ unsigned Bs[2][BK][LDAS];

    int tid = threadIdx.x;
    int lane = tid & 31;
    int warp = tid >> 5;
    int grp = lane >> 2;      // 0..7
    int tig = lane & 3;       // 0..3
    int wm = (warp & 3) * 32; // warp M base within block tile
    int wn = (warp >> 2) * 64;// warp N base within block tile

    int bm = blockIdx.y * 128;
    int bn = blockIdx.x * 128;

    // A loader: thread -> (row, 8-col chunk)
    int aRow = tid >> 1;
    int aSub = (tid & 1) * 8;
    const float* Aptr = A + (size_t)(bm + aRow) * K + aSub;
    float lm = 0.f, lr = 0.f;
    if (FLN) { lm = g_mean[bm + aRow]; lr = g_rstd[bm + aRow]; }

    // B loader: thread -> (k-row, 8-col chunk)
    int bRow = tid >> 4;
    int bCol = (tid & 15) * 8;
    const float* Bptr = Bw + (size_t)bRow * Nn + bn + bCol;

    float acc[2][8][4];
    #pragma unroll
    for (int mt = 0; mt < 2; mt++)
        #pragma unroll
        for (int nt = 0; nt < 8; nt++)
            #pragma unroll
            for (int i = 0; i < 4; i++) acc[mt][nt][i] = 0.f;

    int nsteps = K / BK;
    float4 pa0, pa1, pb0, pb1;

    // prologue: load tile 0
    {
        pa0 = *(const float4*)(Aptr);
        pa1 = *(const float4*)(Aptr + 4);
        pb0 = *(const float4*)(Bptr);
        pb1 = *(const float4*)(Bptr + 4);
        Aptr += BK;
        Bptr += (size_t)BK * Nn;
    }
    // store tile 0 into buf 0
    {
        float av[8] = {pa0.x, pa0.y, pa0.z, pa0.w, pa1.x, pa1.y, pa1.z, pa1.w};
        if (FLN) {
            #pragma unroll
            for (int j = 0; j < 8; j++) {
                int kk = aSub + j;
                av[j] = (av[j] - lm) * lr * __ldg(&lng[kk]) + __ldg(&lnb[kk]);
            }
        }
        #pragma unroll
        for (int j = 0; j < 8; j++) As[0][aSub + j][aRow] = f2tf32(av[j]);
        unsigned u[8] = {f2tf32(pb0.x), f2tf32(pb0.y), f2tf32(pb0.z), f2tf32(pb0.w),
                         f2tf32(pb1.x), f2tf32(pb1.y), f2tf32(pb1.z), f2tf32(pb1.w)};
        *(uint4*)&Bs[0][bRow][bCol]     = make_uint4(u[0], u[1], u[2], u[3]);
        *(uint4*)&Bs[0][bRow][bCol + 4] = make_uint4(u[4], u[5], u[6], u[7]);
    }
    __syncthreads();

    for (int s = 0; s < nsteps; s++) {
        int buf = s & 1;
        bool more = (s + 1 < nsteps);
        if (more) {
            pa0 = *(const float4*)(Aptr);
            pa1 = *(const float4*)(Aptr + 4);
            pb0 = *(const float4*)(Bptr);
            pb1 = *(const float4*)(Bptr + 4);
            Aptr += BK;
            Bptr += (size_t)BK * Nn;
        }

        // compute on current buffer: two k-chunks of 8
        #pragma unroll
        for (int kc = 0; kc < BK; kc += 8) {
            unsigned afr[2][4], bfr[8][2];
            #pragma unroll
            for (int mt = 0; mt < 2; mt++) {
                int m0 = wm + mt * 16 + grp;
                afr[mt][0] = As[buf][kc + tig][m0];
                afr[mt][1] = As[buf][kc + tig][m0 + 8];
                afr[mt][2] = As[buf][kc + 4 + tig][m0];
                afr[mt][3] = As[buf][kc + 4 + tig][m0 + 8];
            }
            #pragma unroll
            for (int nt = 0; nt < 8; nt++) {
                int n0 = wn + nt * 8 + grp;
                bfr[nt][0] = Bs[buf][kc + tig][n0];
                bfr[nt][1] = Bs[buf][kc + 4 + tig][n0];
            }
            #pragma unroll
            for (int mt = 0; mt < 2; mt++)
                #pragma unroll
                for (int nt = 0; nt < 8; nt++)
                    mma_tf32(acc[mt][nt], afr[mt], bfr[nt]);
        }

        if (more) {
            int nb = buf ^ 1;
            float av[8] = {pa0.x, pa0.y, pa0.z, pa0.w, pa1.x, pa1.y, pa1.z, pa1.w};
            if (FLN) {
                int kbase = (s + 1) * BK + aSub;
                #pragma unroll
                for (int j = 0; j < 8; j++)
                    av[j] = (av[j] - lm) * lr * __ldg(&lng[kbase + j]) + __ldg(&lnb[kbase + j]);
            }
            #pragma unroll
            for (int j = 0; j < 8; j++) As[nb][aSub + j][aRow] = f2tf32(av[j]);
            unsigned u[8] = {f2tf32(pb0.x), f2tf32(pb0.y), f2tf32(pb0.z), f2tf32(pb0.w),
                             f2tf32(pb1.x), f2tf32(pb1.y), f2tf32(pb1.z), f2tf32(pb1.w)};
            *(uint4*)&Bs[nb][bRow][bCol]     = make_uint4(u[0], u[1], u[2], u[3]);
            *(uint4*)&Bs[nb][bRow][bCol + 4] = make_uint4(u[4], u[5], u[6], u[7]);
        }
        __syncthreads();
    }

    // epilogue
    #pragma unroll
    for (int mt = 0; mt < 2; mt++) {
        int row = bm + wm + mt * 16 + grp;
        #pragma unroll
        for (int nt = 0; nt < 8; nt++) {
            int col = bn + wn + nt * 8 + tig * 2;
            float c0 = acc[mt][nt][0], c1 = acc[mt][nt][1];
            float c2 = acc[mt][nt][2], c3 = acc[mt][nt][3];
            if (BIAS) {
                float b0 = bias[col], b1 = bias[col + 1];
                c0 += b0; c1 += b1; c2 += b0; c3 += b1;
            }
            if (RELU) {
                c0 = fmaxf(c0, 0.f); c1 = fmaxf(c1, 0.f);
                c2 = fmaxf(c2, 0.f); c3 = fmaxf(c3, 0.f);
            }
            *(float2*)(C + (size_t)row * Nn + col)       = make_float2(c0, c1);
            *(float2*)(C + (size_t)(row + 8) * Nn + col) = make_float2(c2, c3);
        }
    }
}

// ---------------- block mean/var helper for 256-wide rows --------------------
__device__ __forceinline__ float2 block_meanvar_256(float v, float* r1, float* r2) {
    float s = v, q = v * v;
    #pragma unroll
    for (int o = 16; o; o >>= 1) {
        s += __shfl_xor_sync(0xffffffffu, s, o);
        q += __shfl_xor_sync(0xffffffffu, q, o);
    }
    int w = threadIdx.x >> 5, lane = threadIdx.x & 31;
    if (lane == 0) { r1[w] = s; r2[w] = q; }
    __syncthreads();
    float sum = 0.f, sq = 0.f;
    #pragma unroll
    for (int i = 0; i < 8; i++) { sum += r1[i]; sq += r2[i]; }
    __syncthreads();
    float m = sum * (1.f / 256.f);
    float var = sq * (1.f / 256.f) - m * m;
    return make_float2(m, rsqrtf(var + 1e-5f));
}

// ---------------- LN over 256-wide rows: feats = LN(h2) ----------------------
__global__ void ln256_kernel(const float* __restrict__ x, float* __restrict__ y,
                             const float* __restrict__ g, const float* __restrict__ b) {
    __shared__ float r1[8], r2[8];
    size_t row = blockIdx.x;
    int tid = threadIdx.x;
    float v = x[row * DD + tid];
    float2 mv = block_meanvar_256(v, r1, r2);
    y[row * DD + tid] = (v - mv.x) * mv.y * g[tid] + b[tid];
}

// ---------------- q = LN(slots) @ wq^T (block per (b,s) row) -----------------
__global__ void qproj_kernel(const float* __restrict__ ng, const float* __restrict__ nb) {
    __shared__ float sln[DD];
    __shared__ float r1[8], r2[8];
    int row = blockIdx.x, tid = threadIdx.x;
    float v = g_slots[row * DD + tid];
    float2 mv = block_meanvar_256(v, r1, r2);
    sln[tid] = (v - mv.x) * mv.y * ng[tid] + nb[tid];
    __syncthreads();
    float acc = 0.f;
    #pragma unroll 8
    for (int d = 0; d < DD; d++) acc += sln[d] * g_wqT[d * DD + tid];
    g_q[row * DD + tid] = acc;
}

// ---------------- attention: U += attn_u @ V, rowsum += sum_t attn_u ---------
__global__ void __launch_bounds__(256)
attn_kernel() {
    int b = blockIdx.x, ch = blockIdx.y;
    int warp = threadIdx.x >> 5, lane = threadIdx.x & 31;
    __shared__ float qs[NS * DD];
    __shared__ float dots[8][NS];
    for (int i = threadIdx.x; i < NS * DD; i += 256) qs[i] = g_q[b * NS * DD + i];
    __syncthreads();
    float qreg[8];
    #pragma unroll
    for (int j = 0; j < 8; j++) qreg[j] = qs[warp * DD + lane + 32 * j];
    float uacc[8];
    #pragma unroll
    for (int j = 0; j < 8; j++) uacc[j] = 0.f;
    float rsum = 0.f;
    const float scale = 0.0625f;
    int t0 = ch * 512;
    const float* kb = g_keys + ((size_t)b * NTOK + t0) * DD;
    const float* vb = g_vals + ((size_t)b * NTOK + t0) * DD;

    for (int tt = 0; tt < 512; tt += 8) {
        #pragma unroll
        for (int u = 0; u < 8; u++) {
            const float* kp = kb + (size_t)(tt + u) * DD;
            float d = 0.f;
            #pragma unroll
            for (int j = 0; j < 8; j++) d += qreg[j] * kp[lane + 32 * j];
            #pragma unroll
            for (int o = 16; o; o >>= 1) d += __shfl_xor_sync(0xffffffffu, d, o);
            if (lane == 0) dots[u][warp] = d * scale;
        }
        __syncthreads();
        #pragma unroll
        for (int u = 0; u < 8; u++) {
            float mx = -1e30f;
            #pragma unroll
            for (int s2 = 0; s2 < NS; s2++) mx = fmaxf(mx, dots[u][s2]);
            float sume = 0.f;
            #pragma unroll
            for (int s2 = 0; s2 < NS; s2++) sume += expf(dots[u][s2] - mx);
            float a = expf(dots[u][warp] - mx) / sume + 1e-8f;
            const float* vp = vb + (size_t)(tt + u) * DD;
            #pragma unroll
            for (int j = 0; j < 8; j++) uacc[j] += a * vp[lane + 32 * j];
            rsum += a;
        }
        __syncthreads();
    }
    float* up = g_U + (b * NS + warp) * DD;
    #pragma unroll
    for (int j = 0; j < 8; j++) atomicAdd(&up[lane + 32 * j], uacc[j]);
    if (lane == 0) atomicAdd(&g_rowsum[b * NS + warp], rsum);
}

// ---------------- GRU cell + residual pre-LN MLP (block per (b,s) row) -------
__global__ void __launch_bounds__(256)
gru_mlp_kernel(const float* __restrict__ bih, const float* __restrict__ bhh,
               const float* __restrict__ mlng, const float* __restrict__ mlnb,
               const float* __restrict__ w1, const float* __restrict__ b1,
               const float* __restrict__ w2, const float* __restrict__ b2) {
    __shared__ float upd[DD], sp[DD], mm[DD];
    __shared__ float hh[4 * DD];
    __shared__ float r1[8], r2[8];
    int row = blockIdx.x, tid = threadIdx.x;
    float rs = g_rowsum[row];
    upd[tid] = g_U[row * DD + tid] / rs;
    sp[tid]  = g_slots[row * DD + tid];
    __syncthreads();

    float ir = bih[tid], iz = bih[tid + 256], inn = bih[tid + 512];
    float hr = bhh[tid], hz = bhh[tid + 256], hn = bhh[tid + 512];
    #pragma unroll 4
    for (int d = 0; d < DD; d++) {
        float u = upd[d], s = sp[d];
        const float* wi = &g_wihT[d * 768];
        const float* wh = &g_whhT[d * 768];
        ir  += u * wi[tid];       hr  += s * wh[tid];
        iz  += u * wi[tid + 256]; hz  += s * wh[tid + 256];
        inn += u * wi[tid + 512]; hn  += s * wh[tid + 512];
    }
    float r = 1.f / (1.f + expf(-(ir + hr)));
    float z = 1.f / (1.f + expf(-(iz + hz)));
    float n = tanhf(inn + r * hn);
    float h = (1.f - z) * n + z * sp[tid];
    __syncthreads();

    float2 mv = block_meanvar_256(h, r1, r2);
    mm[tid] = (h - mv.x) * mv.y * mlng[tid] + mlnb[tid];
    __syncthreads();

    #pragma unroll
    for (int jj = 0; jj < 4; jj++) {
        int o = tid + jj * 256;
        float a = b1[o];
        #pragma unroll 8
        for (int d = 0; d < DD; d++) a += mm[d] * w1[d * 1024 + o];
        hh[o] = fmaxf(a, 0.f);
    }
    __syncthreads();
    float a2 = b2[tid];
    #pragma unroll 8
    for (int j = 0; j < 1024; j++) a2 += hh[j] * w2[j * 256 + tid];
    g_slots[row * DD + tid] = h + a2;
}

// ---------------- launch ----------------
extern "C" void kernel_launch(void* const* d_in, const int* in_sizes, int n_in,
                              void* d_out, int out_size) {
    const float* inputs   = (const float*)d_in[0];
    const float* slots_in = (const float*)d_in[1];
    const float* ln1g = (const float*)d_in[2];
    const float* ln1b = (const float*)d_in[3];
    const float* w1   = (const float*)d_in[4];
    const float* b1   = (const float*)d_in[5];
    const float* w2   = (const float*)d_in[6];
    const float* b2   = (const float*)d_in[7];
    const float* ln2g = (const float*)d_in[8];
    const float* ln2b = (const float*)d_in[9];
    const float* wq   = (const float*)d_in[10];
    const float* wk   = (const float*)d_in[11];
    const float* wv   = (const float*)d_in[12];
    const float* normg = (const float*)d_in[13];
    const float* normb = (const float*)d_in[14];
    const float* gwih = (const float*)d_in[15];
    const float* gwhh = (const float*)d_in[16];
    const float* gbih = (const float*)d_in[17];
    const float* gbhh = (const float*)d_in[18];
    const float* mlng = (const float*)d_in[19];
    const float* mlnb = (const float*)d_in[20];
    const float* mw1  = (const float*)d_in[21];
    const float* mb1  = (const float*)d_in[22];
    const float* mw2  = (const float*)d_in[23];
    const float* mb2  = (const float*)d_in[24];
    float* out = (float*)d_out;

    float *p_wkT, *p_wvT, *p_wqT, *p_wihT, *p_whhT;
    float *p_h1, *p_h2, *p_feats, *p_keys, *p_vals;
    cudaGetSymbolAddress((void**)&p_wkT,  g_wkT);
    cudaGetSymbolAddress((void**)&p_wvT,  g_wvT);
    cudaGetSymbolAddress((void**)&p_wqT,  g_wqT);
    cudaGetSymbolAddress((void**)&p_wihT, g_wihT);
    cudaGetSymbolAddress((void**)&p_whhT, g_whhT);
    cudaGetSymbolAddress((void**)&p_h1,   g_h1);
    cudaGetSymbolAddress((void**)&p_h2,   g_h2);
    cudaGetSymbolAddress((void**)&p_feats, g_feats);
    cudaGetSymbolAddress((void**)&p_keys, g_keys);
    cudaGetSymbolAddress((void**)&p_vals, g_vals);

    // weight transposes (tiny)
    transpose_kernel<<<(DD * DD + 255) / 256, 256>>>(wk, p_wkT, DD, DD);
    transpose_kernel<<<(DD * DD + 255) / 256, 256>>>(wv, p_wvT, DD, DD);
    transpose_kernel<<<(DD * DD + 255) / 256, 256>>>(wq, p_wqT, DD, DD);
    transpose_kernel<<<(3 * DD * DD + 255) / 256, 256>>>(gwih, p_wihT, 3 * DD, DD);
    transpose_kernel<<<(3 * DD * DD + 255) / 256, 256>>>(gwhh, p_whhT, 3 * DD, DD);

    // feature path (tensor-core tf32 GEMMs)
    ln_stats_kernel<<<MROWS / 8, 256>>>(inputs);
    tf32_gemm_kernel<true, true, true><<<dim3(FDIN / 128, MROWS / 128), 256>>>(
        inputs, w1, b1, p_h1, MROWS, FDIN, FDIN, ln1g, ln1b);
    tf32_gemm_kernel<false, false, true><<<dim3(DD / 128, MROWS / 128), 256>>>(
        p_h1, w2, b2, p_h2, MROWS, DD, FDIN, nullptr, nullptr);
    ln256_kernel<<<MROWS, 256>>>(p_h2, p_feats, ln2g, ln2b);
    tf32_gemm_kernel<false, false, false><<<dim3(DD / 128, MROWS / 128), 256>>>(
        p_feats, p_wkT, nullptr, p_keys, MROWS, DD, DD, nullptr, nullptr);
    tf32_gemm_kernel<false, false, false><<<dim3(DD / 128, MROWS / 128), 256>>>(
        p_feats, p_wvT, nullptr, p_vals, MROWS, DD, DD, nullptr, nullptr);

    // slot init
    slots_init_kernel<<<BNUM * NS * DD / 256, 256>>>(slots_in);

    // iterations (straight-through in iter 3 is a forward identity)
    for (int t = 0; t < ITERS; t++) {
        qproj_kernel<<<BNUM * NS, 256>>>(normg, normb);
        zero_ur_kernel<<<BNUM * NS * DD / 256, 256>>>();
        attn_kernel<<<dim3(BNUM, 8), 256>>>();
        gru_mlp_kernel<<<BNUM * NS, 256>>>(gbih, gbhh, mlng, mlnb, mw1, mb1, mw2, mb2);
    }

    copy_out_kernel<<<BNUM * NS * DD / 256, 256>>>(out);
}